// round 16
// baseline (speedup 1.0000x reference)
#include <cuda_runtime.h>
#include <cstdint>

// BatchedGAT round 15:
//   wfrag_kernel: W -> fp16 m16n8k16 B-fragments (unchanged).
//   gemm_mma: h = x@W fp16 k16 (unchanged mainloop). Epilogue now stores
//             PRE-EXPONENTIATED source terms: g_es1 = 2^(es'), g_es2 =
//             2^(0.2 es')  (es' = e_src*log2e).
//   attn: exp(leaky(ed+es)) == max(2^ed'*2^es', 2^.2ed'*2^.2es') (monotone
//         exp) -> inner loop has ZERO MUFU: 2 FMUL + FMNMX + SEL per element.
//         ed-side exps computed once in the prologue.

#define DEV __device__ __forceinline__
using u64 = unsigned long long;
using u32 = unsigned int;

DEV float ex2f(float x) {
    float r; asm("ex2.approx.f32 %0, %1;" : "=f"(r) : "f"(x)); return r;
}
// pack {lo, hi} floats -> f16x2 (lo in low half)
DEV u32 packhf(float lo, float hi) {
    u32 r; asm("cvt.rn.f16x2.f32 %0, %1, %2;" : "=r"(r) : "f"(hi), "f"(lo));
    return r;
}
DEV u32 smem_u32(const void* p) {
    u32 a; asm("{ .reg .u64 t; cvta.to.shared.u64 t, %1; cvt.u32.u64 %0, t; }"
               : "=r"(a) : "l"(p));
    return a;
}
DEV void cpasync16(u32 dst, const void* src) {
    asm volatile("cp.async.cg.shared.global [%0], [%1], 16;"
                 :: "r"(dst), "l"(src) : "memory");
}
#define CP_COMMIT() asm volatile("cp.async.commit_group;" ::: "memory")
#define CP_WAIT1()  asm volatile("cp.async.wait_group 1;" ::: "memory")
#define CP_WAIT0()  asm volatile("cp.async.wait_group 0;" ::: "memory")

DEV void mma16n8k16hf(float* c, u32 a0, u32 a1, u32 a2, u32 a3, u32 b0, u32 b1) {
    asm volatile(
        "mma.sync.aligned.m16n8k16.row.col.f32.f16.f16.f32 "
        "{%0,%1,%2,%3}, {%4,%5,%6,%7}, {%8,%9}, {%0,%1,%2,%3};"
        : "+f"(c[0]), "+f"(c[1]), "+f"(c[2]), "+f"(c[3])
        : "r"(a0), "r"(a1), "r"(a2), "r"(a3), "r"(b0), "r"(b1));
}

constexpr int Bb = 16, Nn = 1024, Dd = 256, Hh = 4, HF = 256;
constexpr int Mrows = Bb * Nn;
constexpr float LOG2E = 1.4426950408889634f;

// Pre-exponentiated source terms [h][b*N+n]:
__device__ float g_es1[Hh * Mrows];   // 2^(es * log2e)
__device__ float g_es2[Hh * Mrows];   // 2^(0.2 * es * log2e)
__device__ float g_ed[Hh * Mrows];    // raw ed * log2e
// attn B fragments (fp16 m16n8k16): [bh][jb16(64)][nf(8)][lane(32)] uint2
__device__ uint2 g_hBf[64 * 64 * 8 * 32];     // 8.4 MB
// W fragments (fp16 m16n8k16): [bn(4)][k16(16)][nf(8)][lane(32)] uint2
__device__ uint2 g_wf16[4 * 16 * 8 * 32];     // 128 KB

// ---------------------------------------------------------------------------
// Kernel 0: W -> fp16 m16n8k16 B-fragment layout (col-major).
// ---------------------------------------------------------------------------
__global__ __launch_bounds__(256) void wfrag_kernel(const float* __restrict__ W) {
    const int v = blockIdx.x * 256 + threadIdx.x;   // 0..16383
    const int bn = v >> 12;
    const int k16 = (v >> 8) & 15;
    const int nf = (v >> 5) & 7;
    const int ln = v & 31;
    const int k = (k16 << 4) + ((ln & 3) << 1);
    const int col = bn * 64 + (nf << 3) + (ln >> 2);
    uint2 o;
    o.x = packhf(__ldg(&W[k * HF + col]),       __ldg(&W[(k + 1) * HF + col]));
    o.y = packhf(__ldg(&W[(k + 8) * HF + col]), __ldg(&W[(k + 9) * HF + col]));
    g_wf16[((bn * 16 + k16) * 8 + nf) * 32 + ln] = o;
}

// ---------------------------------------------------------------------------
// Kernel 1: gemm via mma.sync fp16 k16 + fused e + fp16 attn-frag emission.
// Grid 128 (bm), 512 thr, 16 warps. Warp w: rg=w>>2 (rows), cg=w&3 (head).
// ---------------------------------------------------------------------------
constexpr int XROW = 36;
constexpr int GOFF_X0  = 0;               // 18432
constexpr int GOFF_X1  = 18432;
constexpr int GOFF_WF0 = 36864;           // 16384
constexpr int GOFF_WF1 = 53248;
constexpr int SMEM_GEMM = 69632;          // hs[128][68] (34816) unioned at 0

__global__ __launch_bounds__(512) void gemm_mma(const float* __restrict__ A,
                                                const float* __restrict__ a_src,
                                                const float* __restrict__ a_dst) {
    extern __shared__ char gsm[];
    const u32 sbase = smem_u32(gsm);

    const int tid = threadIdx.x;
    const int w = tid >> 5, lane = tid & 31;
    const int bm = blockIdx.x;
    const int rg = w >> 2, cg = w & 3;
    const int grp = lane >> 2;
    const int tig = lane & 3;
    const int r0 = rg * 16;

    const u32 x_off[2]  = { sbase + GOFF_X0,  sbase + GOFF_X1 };
    const u32 wf_off[2] = { sbase + GOFF_WF0, sbase + GOFF_WF1 };

    auto stage = [&](int s, int sel) {
#pragma unroll
        for (int q = 0; q < 2; ++q) {
            int v = (q << 9) + tid;
            int row = v >> 3, c4 = (v & 7) << 2;
            cpasync16(x_off[sel] + (u32)(row * XROW + c4) * 4u,
                      A + (size_t)(bm * 128 + row) * Dd + (s << 5) + c4);
        }
#pragma unroll
        for (int q = 0; q < 2; ++q) {
            int v = (q << 9) + tid;       // 0..1023
            int bn = v >> 8;
            int rest = v & 255;
            const uint4* src = (const uint4*)(g_wf16 + (size_t)((bn * 16 + (s << 1)) * 8) * 32) + rest;
            cpasync16(wf_off[sel] + (u32)(bn * 256 + rest) * 16u, src);
        }
    };

    float acc0[8][4], acc1[8][4];
#pragma unroll
    for (int n = 0; n < 8; ++n)
#pragma unroll
        for (int k = 0; k < 4; ++k) { acc0[n][k] = 0.f; acc1[n][k] = 0.f; }

    stage(0, 0); CP_COMMIT();

    for (int s = 0; s < 8; ++s) {
        const int sel = s & 1;
        if (s < 7) { stage(s + 1, sel ^ 1); CP_COMMIT(); }
        if (s < 7) CP_WAIT1(); else CP_WAIT0();
        __syncthreads();

        const float* xs = (const float*)(gsm + (sel ? GOFF_X1 : GOFF_X0));
        const uint2* wfs = (const uint2*)(gsm + (sel ? GOFF_WF1 : GOFF_WF0));

#pragma unroll
        for (int kb = 0; kb < 2; ++kb) {
            const int kc = (kb << 4) + (tig << 1);
            float2 v0a = *(const float2*)&xs[(r0 + grp) * XROW + kc];
            float2 v0b = *(const float2*)&xs[(r0 + grp) * XROW + kc + 8];
            float2 v1a = *(const float2*)&xs[(r0 + 8 + grp) * XROW + kc];
            float2 v1b = *(const float2*)&xs[(r0 + 8 + grp) * XROW + kc + 8];
            float2 v2a = *(const float2*)&xs[(64 + r0 + grp) * XROW + kc];
            float2 v2b = *(const float2*)&xs[(64 + r0 + grp) * XROW + kc + 8];
            float2 v3a = *(const float2*)&xs[(64 + r0 + 8 + grp) * XROW + kc];
            float2 v3b = *(const float2*)&xs[(64 + r0 + 8 + grp) * XROW + kc + 8];
            u32 a0 = packhf(v0a.x, v0a.y);
            u32 a1 = packhf(v1a.x, v1a.y);
            u32 a2 = packhf(v0b.x, v0b.y);
            u32 a3 = packhf(v1b.x, v1b.y);
            u32 a4 = packhf(v2a.x, v2a.y);
            u32 a5 = packhf(v3a.x, v3a.y);
            u32 a6 = packhf(v2b.x, v2b.y);
            u32 a7 = packhf(v3b.x, v3b.y);
            const uint2* wr = wfs + (((cg << 1) + kb) << 8) + lane;
#pragma unroll
            for (int n = 0; n < 8; ++n) {
                uint2 bf = wr[n << 5];
                mma16n8k16hf(acc0[n], a0, a1, a2, a3, bf.x, bf.y);
                mma16n8k16hf(acc1[n], a4, a5, a6, a7, bf.x, bf.y);
            }
        }
        __syncthreads();
    }

    // ---- e_src/e_dst: warp-local; es stored PRE-EXPONENTIATED ----
    {
        float ps0 = 0.f, ps1 = 0.f, pd0 = 0.f, pd1 = 0.f;
        float qs0 = 0.f, qs1 = 0.f, qd0 = 0.f, qd1 = 0.f;
#pragma unroll
        for (int n = 0; n < 8; ++n) {
            float2 asv = *(const float2*)&a_src[cg * 64 + (n << 3) + (tig << 1)];
            float2 adv = *(const float2*)&a_dst[cg * 64 + (n << 3) + (tig << 1)];
            ps0 = fmaf(acc0[n][0], asv.x, fmaf(acc0[n][1], asv.y, ps0));
            ps1 = fmaf(acc0[n][2], asv.x, fmaf(acc0[n][3], asv.y, ps1));
            pd0 = fmaf(acc0[n][0], adv.x, fmaf(acc0[n][1], adv.y, pd0));
            pd1 = fmaf(acc0[n][2], adv.x, fmaf(acc0[n][3], adv.y, pd1));
            qs0 = fmaf(acc1[n][0], asv.x, fmaf(acc1[n][1], asv.y, qs0));
            qs1 = fmaf(acc1[n][2], asv.x, fmaf(acc1[n][3], asv.y, qs1));
            qd0 = fmaf(acc1[n][0], adv.x, fmaf(acc1[n][1], adv.y, qd0));
            qd1 = fmaf(acc1[n][2], adv.x, fmaf(acc1[n][3], adv.y, qd1));
        }
#pragma unroll
        for (int o = 1; o < 4; o <<= 1) {
            ps0 += __shfl_xor_sync(0xffffffffu, ps0, o);
            ps1 += __shfl_xor_sync(0xffffffffu, ps1, o);
            pd0 += __shfl_xor_sync(0xffffffffu, pd0, o);
            pd1 += __shfl_xor_sync(0xffffffffu, pd1, o);
            qs0 += __shfl_xor_sync(0xffffffffu, qs0, o);
            qs1 += __shfl_xor_sync(0xffffffffu, qs1, o);
            qd0 += __shfl_xor_sync(0xffffffffu, qd0, o);
            qd1 += __shfl_xor_sync(0xffffffffu, qd1, o);
        }
        if (tig == 0) {
            const int base = cg * Mrows + bm * 128;
            float e;
            e = ps0 * LOG2E;
            g_es1[base + r0 + grp] = ex2f(e);  g_es2[base + r0 + grp] = ex2f(0.2f * e);
            e = ps1 * LOG2E;
            g_es1[base + r0 + 8 + grp] = ex2f(e);  g_es2[base + r0 + 8 + grp] = ex2f(0.2f * e);
            e = qs0 * LOG2E;
            g_es1[base + 64 + r0 + grp] = ex2f(e);  g_es2[base + 64 + r0 + grp] = ex2f(0.2f * e);
            e = qs1 * LOG2E;
            g_es1[base + 64 + r0 + 8 + grp] = ex2f(e);  g_es2[base + 64 + r0 + 8 + grp] = ex2f(0.2f * e);
            g_ed[base + r0 + grp]           = pd0 * LOG2E;
            g_ed[base + r0 + 8 + grp]       = pd1 * LOG2E;
            g_ed[base + 64 + r0 + grp]      = qd0 * LOG2E;
            g_ed[base + 64 + r0 + 8 + grp]  = qd1 * LOG2E;
        }
    }

    // ---- per-head hs bounce + fp16 fragment emission ----
    float (*hs)[68] = (float(*)[68])gsm;
    const int b_ = bm >> 3;

    for (int hh = 0; hh < 4; ++hh) {
        __syncthreads();
        if (cg == hh) {
#pragma unroll
            for (int n = 0; n < 8; ++n) {
                const int col = (n << 3) + (tig << 1);
                hs[r0 + grp][col]          = acc0[n][0];
                hs[r0 + grp][col + 1]      = acc0[n][1];
                hs[r0 + 8 + grp][col]      = acc0[n][2];
                hs[r0 + 8 + grp][col + 1]  = acc0[n][3];
                hs[64 + r0 + grp][col]         = acc1[n][0];
                hs[64 + r0 + grp][col + 1]     = acc1[n][1];
                hs[64 + r0 + 8 + grp][col]     = acc1[n][2];
                hs[64 + r0 + 8 + grp][col + 1] = acc1[n][3];
            }
        }
        __syncthreads();

        const int bh = b_ * 4 + hh;
#pragma unroll
        for (int q2 = 0; q2 < 4; ++q2) {
            int v = (q2 << 9) + tid;       // 0..2047
            int jbl = v >> 8;
            int nf = (v >> 5) & 7;
            int ln = v & 31;
            int jl = (jbl << 4) + ((ln & 3) << 1);
            int f = (nf << 3) + (ln >> 2);
            uint2 o;
            o.x = packhf(hs[jl][f],     hs[jl + 1][f]);
            o.y = packhf(hs[jl + 8][f], hs[jl + 9][f]);
            g_hBf[(size_t)(((bh * 64 + (bm & 7) * 8 + jbl) * 8 + nf)) * 32 + ln] = o;
        }
    }
}

// ---------------------------------------------------------------------------
// Kernel 2: flash-GAT attention, fp16 m16n8k16, MUFU-free inner loop.
// ---------------------------------------------------------------------------
constexpr int ADJ_ST = 68;
constexpr int OFF_ADJ0  = 0;                   // 34816
constexpr int OFF_ADJ1  = 34816;
constexpr int OFF_HF0   = 69632;               // 8192
constexpr int OFF_HF1   = 77824;
constexpr int OFF_ES1_0 = 86016;               // 256
constexpr int OFF_ES1_1 = 86272;
constexpr int OFF_ES2_0 = 86528;
constexpr int OFF_ES2_1 = 86784;
constexpr int OFF_ED1   = 87040;               // 512
constexpr int OFF_ED2   = 87552;               // 512
constexpr int OFF_DEN   = 88064;               // 512
constexpr int SMEM_ATTN = 88576;

__global__ __launch_bounds__(256, 2) void attn_kernel(const float* __restrict__ adj,
                                                      const float* __restrict__ bias,
                                                      float* __restrict__ out) {
    extern __shared__ char dsm[];
    const u32 sbase = smem_u32(dsm);
    float* ed1_sm = (float*)(dsm + OFF_ED1);
    float* ed2_sm = (float*)(dsm + OFF_ED2);
    float* den_sm = (float*)(dsm + OFF_DEN);

    const int tid = threadIdx.x;
    const int w = tid >> 5, lane = tid & 31;
    const int bh = blockIdx.y, b = bh >> 2, h = bh & 3;
    const int i0 = blockIdx.x << 7;
    const int i_w = w << 4;
    const int grp = lane >> 2;
    const int tig = lane & 3;

    const u32 adj_off[2] = { sbase + OFF_ADJ0, sbase + OFF_ADJ1 };
    const u32 hf_off[2]  = { sbase + OFF_HF0,  sbase + OFF_HF1 };
    const u32 es1_off[2] = { sbase + OFF_ES1_0, sbase + OFF_ES1_1 };
    const u32 es2_off[2] = { sbase + OFF_ES2_0, sbase + OFF_ES2_1 };

    const float* adj_base = adj + (size_t)(b * Nn + i0) * Nn;
    const uint2* hf_base = g_hBf + (size_t)bh * 64 * 8 * 32;
    const float* es1_base = g_es1 + h * Mrows + b * Nn;
    const float* es2_base = g_es2 + h * Mrows + b * Nn;

    auto stage = [&](int jt, int sel) {
        const int j0 = jt << 6;
        const int r = tid >> 4, c4 = (tid & 15) << 2;
#pragma unroll
        for (int q = 0; q < 8; ++q)
            cpasync16(adj_off[sel] + (u32)(((q << 4) + r) * ADJ_ST + c4) * 4u,
                      adj_base + (size_t)((q << 4) + r) * Nn + j0 + c4);
        const uint4* hsrc = (const uint4*)(hf_base + (size_t)(jt * 4) * 8 * 32);
#pragma unroll
        for (int q = 0; q < 2; ++q)
            cpasync16(hf_off[sel] + (u32)((q << 8) + tid) * 16u, hsrc + (q << 8) + tid);
        if (tid < 16)
            cpasync16(es1_off[sel] + (u32)tid * 16u, es1_base + j0 + tid * 4);
        else if (tid < 32)
            cpasync16(es2_off[sel] + (u32)(tid - 16) * 16u, es2_base + j0 + (tid - 16) * 4);
    };

    stage(0, 0); CP_COMMIT();
    if (tid < 128) {
        float ed = g_ed[h * Mrows + b * Nn + i0 + tid];
        ed1_sm[tid] = ex2f(ed);
        ed2_sm[tid] = ex2f(0.2f * ed);
    }

    float acc[8][4];
#pragma unroll
    for (int n = 0; n < 8; ++n)
#pragma unroll
        for (int k = 0; k < 4; ++k) acc[n][k] = 0.f;
    float den0 = 0.f, den1 = 0.f;

    __syncthreads();
    const float d10 = ed1_sm[i_w + grp],     d20 = ed2_sm[i_w + grp];
    const float d11 = ed1_sm[i_w + 8 + grp], d21 = ed2_sm[i_w + 8 + grp];

    for (int jt = 0; jt < 16; ++jt) {
        const int sel = jt & 1;
        if (jt < 15) { stage(jt + 1, sel ^ 1); CP_COMMIT(); }
        if (jt < 15) CP_WAIT1(); else CP_WAIT0();
        __syncthreads();

        const float* adj_sm = (const float*)(dsm + (sel ? OFF_ADJ1 : OFF_ADJ0));
        const uint2* hfrag  = (const uint2*)(dsm + (sel ? OFF_HF1 : OFF_HF0));
        const float* es1_sm = (const float*)(dsm + (sel ? OFF_ES1_1 : OFF_ES1_0));
        const float* es2_sm = (const float*)(dsm + (sel ? OFF_ES2_1 : OFF_ES2_0));

#pragma unroll
        for (int ks = 0; ks < 4; ++ks) {
            const int jj = (ks << 4) + (tig << 1);
            float2 s1A = *(const float2*)&es1_sm[jj];
            float2 s1B = *(const float2*)&es1_sm[jj + 8];
            float2 s2A = *(const float2*)&es2_sm[jj];
            float2 s2B = *(const float2*)&es2_sm[jj + 8];
            float2 aj0 = *(const float2*)&adj_sm[(i_w + grp) * ADJ_ST + jj];
            float2 aj1 = *(const float2*)&adj_sm[(i_w + 8 + grp) * ADJ_ST + jj];
            float2 aj2 = *(const float2*)&adj_sm[(i_w + grp) * ADJ_ST + jj + 8];
            float2 aj3 = *(const float2*)&adj_sm[(i_w + 8 + grp) * ADJ_ST + jj + 8];

            // p = max(E1d*E1s, E2d*E2s)  ==  exp(leaky(ed+es))
            float p00 = fmaxf(d10 * s1A.x, d20 * s2A.x);
            float p01 = fmaxf(d10 * s1A.y, d20 * s2A.y);
            float p02 = fmaxf(d10 * s1B.x, d20 * s2B.x);
            float p03 = fmaxf(d10 * s1B.y, d20 * s2B.y);
            float p10 = fmaxf(d11 * s1A.x, d21 * s2A.x);
            float p11 = fmaxf(d11 * s1A.y, d21 * s2A.y);
            float p12 = fmaxf(d11 * s1B.x, d21 * s2B.x);
            float p13 = fmaxf(d11 * s1B.y, d21 * s2B.y);

            p00 = (aj0.x > 0.5f) ? p00 : 0.f;
            p01 = (aj0.y > 0.5f) ? p01 : 0.f;
            p02 = (aj2.x > 0.5f) ? p02 : 0.f;
            p03 = (aj2.y > 0.5f) ? p03 : 0.f;
            p10 = (aj1.x > 0.5f) ? p10 : 0.f;
            p11 = (aj1.y > 0.5f) ? p11 : 0.f;
            p12 = (aj3.x > 0.5f) ? p12 : 0.f;
            p13 = (aj3.y > 0.5f) ? p13 : 0.f;

            const u32 a0 = packhf(p00, p01);
            const u32 a1 = packhf(p10, p11);
            const u32 a2 = packhf(p02, p03);
            const u32 a3 = packhf(p12, p13);

            den0 += (p00 + p01) + (p02 + p03);
            den1 += (p10 + p11) + (p12 + p13);

            const uint2* hrow = hfrag + (ks << 8) + lane;
#pragma unroll
            for (int n = 0; n < 8; ++n) {
                uint2 bf = hrow[n << 5];
                mma16n8k16hf(acc[n], a0, a1, a2, a3, bf.x, bf.y);
            }
        }
        __syncthreads();
    }

    den0 += __shfl_xor_sync(0xffffffffu, den0, 1);
    den0 += __shfl_xor_sync(0xffffffffu, den0, 2);
    den1 += __shfl_xor_sync(0xffffffffu, den1, 1);
    den1 += __shfl_xor_sync(0xffffffffu, den1, 2);
    if (tig == 0) {
        den_sm[i_w + grp] = den0;
        den_sm[i_w + 8 + grp] = den1;
    }
    __syncthreads();
    const float inv0 = 1.0f / den_sm[i_w + grp];
    const float inv1 = 1.0f / den_sm[i_w + 8 + grp];

    float* o0 = out + (size_t)(b * Nn + i0 + i_w + grp) * HF + h * 64;
    float* o1 = out + (size_t)(b * Nn + i0 + i_w + 8 + grp) * HF + h * 64;
#pragma unroll
    for (int n = 0; n < 8; ++n) {
        const int col = (n << 3) + (tig << 1);
        float2 bz = *(const float2*)&bias[h * 64 + col];
        float2 r0, r1;
        r0.x = acc[n][0] * inv0 + bz.x;  r0.y = acc[n][1] * inv0 + bz.y;
        r1.x = acc[n][2] * inv1 + bz.x;  r1.y = acc[n][3] * inv1 + bz.y;
        *(float2*)&o0[col] = r0;
        *(float2*)&o1[col] = r1;
    }
}

// ---------------------------------------------------------------------------
extern "C" void kernel_launch(void* const* d_in, const int* in_sizes, int n_in,
                              void* d_out, int out_size) {
    (void)in_sizes; (void)n_in; (void)out_size;
    const float* x     = (const float*)d_in[0];
    const float* adj   = (const float*)d_in[1];
    const float* W     = (const float*)d_in[2];
    const float* a_src = (const float*)d_in[3];
    const float* a_dst = (const float*)d_in[4];
    const float* bias  = (const float*)d_in[5];
    float* out = (float*)d_out;

    cudaFuncSetAttribute(gemm_mma,
                         cudaFuncAttributeMaxDynamicSharedMemorySize, SMEM_GEMM);
    cudaFuncSetAttribute(attn_kernel,
                         cudaFuncAttributeMaxDynamicSharedMemorySize, SMEM_ATTN);

    wfrag_kernel<<<64, 256>>>(W);
    gemm_mma<<<128, 512, SMEM_GEMM>>>(x, a_src, a_dst);
    attn_kernel<<<dim3(8, 64), 256, SMEM_ATTN>>>(adj, bias, out);
}

// round 17
// speedup vs baseline: 1.5038x; 1.5038x over previous
#include <cuda_runtime.h>
#include <cstdint>

// BatchedGAT round 16 = R14 (best, 94.7us) + tensor-core denominator:
//   attn appends a virtual ones-column B tile (constant fp16 1.0 operand) so
//   den[i] = sum_j p_ij comes out of an extra MMA per ks -- removes the fp32
//   den FADD chains, the end shfl-reduction, den_sm and one barrier.
//   R15's MUFU-free rewrite is reverted (register spill at the 128-reg cap).
//   wfrag / gemm_mma identical to R14.

#define DEV __device__ __forceinline__
using u64 = unsigned long long;
using u32 = unsigned int;

DEV float ex2f(float x) {
    float r; asm("ex2.approx.f32 %0, %1;" : "=f"(r) : "f"(x)); return r;
}
// pack {lo, hi} floats -> f16x2 (lo in low half)
DEV u32 packhf(float lo, float hi) {
    u32 r; asm("cvt.rn.f16x2.f32 %0, %1, %2;" : "=r"(r) : "f"(hi), "f"(lo));
    return r;
}
DEV u32 smem_u32(const void* p) {
    u32 a; asm("{ .reg .u64 t; cvta.to.shared.u64 t, %1; cvt.u32.u64 %0, t; }"
               : "=r"(a) : "l"(p));
    return a;
}
DEV void cpasync16(u32 dst, const void* src) {
    asm volatile("cp.async.cg.shared.global [%0], [%1], 16;"
                 :: "r"(dst), "l"(src) : "memory");
}
#define CP_COMMIT() asm volatile("cp.async.commit_group;" ::: "memory")
#define CP_WAIT1()  asm volatile("cp.async.wait_group 1;" ::: "memory")
#define CP_WAIT0()  asm volatile("cp.async.wait_group 0;" ::: "memory")

DEV void mma16n8k16hf(float* c, u32 a0, u32 a1, u32 a2, u32 a3, u32 b0, u32 b1) {
    asm volatile(
        "mma.sync.aligned.m16n8k16.row.col.f32.f16.f16.f32 "
        "{%0,%1,%2,%3}, {%4,%5,%6,%7}, {%8,%9}, {%0,%1,%2,%3};"
        : "+f"(c[0]), "+f"(c[1]), "+f"(c[2]), "+f"(c[3])
        : "r"(a0), "r"(a1), "r"(a2), "r"(a3), "r"(b0), "r"(b1));
}

constexpr int Bb = 16, Nn = 1024, Dd = 256, Hh = 4, HF = 256;
constexpr int Mrows = Bb * Nn;
constexpr float LOG2E = 1.4426950408889634f;
constexpr u32 ONE2 = 0x3C003C00u;   // fp16 {1.0, 1.0}

// e arrays transposed [h][b*N+n], PRE-SCALED by log2e.
__device__ float g_es[Hh * Mrows];
__device__ float g_ed[Hh * Mrows];
// attn B fragments (fp16 m16n8k16): [bh][jb16(64)][nf(8)][lane(32)] uint2
__device__ uint2 g_hBf[64 * 64 * 8 * 32];     // 8.4 MB
// W fragments (fp16 m16n8k16): [bn(4)][k16(16)][nf(8)][lane(32)] uint2
__device__ uint2 g_wf16[4 * 16 * 8 * 32];     // 128 KB

// ---------------------------------------------------------------------------
// Kernel 0: W -> fp16 m16n8k16 B-fragment layout (col-major).
// ---------------------------------------------------------------------------
__global__ __launch_bounds__(256) void wfrag_kernel(const float* __restrict__ W) {
    const int v = blockIdx.x * 256 + threadIdx.x;   // 0..16383
    const int bn = v >> 12;
    const int k16 = (v >> 8) & 15;
    const int nf = (v >> 5) & 7;
    const int ln = v & 31;
    const int k = (k16 << 4) + ((ln & 3) << 1);
    const int col = bn * 64 + (nf << 3) + (ln >> 2);
    uint2 o;
    o.x = packhf(__ldg(&W[k * HF + col]),       __ldg(&W[(k + 1) * HF + col]));
    o.y = packhf(__ldg(&W[(k + 8) * HF + col]), __ldg(&W[(k + 9) * HF + col]));
    g_wf16[((bn * 16 + k16) * 8 + nf) * 32 + ln] = o;
}

// ---------------------------------------------------------------------------
// Kernel 1: gemm via mma.sync fp16 k16 + fused e + fp16 attn-frag emission.
// Grid 128 (bm), 512 thr, 16 warps. Warp w: rg=w>>2 (rows), cg=w&3 (head).
// ---------------------------------------------------------------------------
constexpr int XROW = 36;
constexpr int GOFF_X0  = 0;               // 18432
constexpr int GOFF_X1  = 18432;
constexpr int GOFF_WF0 = 36864;           // 16384
constexpr int GOFF_WF1 = 53248;
constexpr int SMEM_GEMM = 69632;          // hs[128][68] (34816) unioned at 0

__global__ __launch_bounds__(512) void gemm_mma(const float* __restrict__ A,
                                                const float* __restrict__ a_src,
                                                const float* __restrict__ a_dst) {
    extern __shared__ char gsm[];
    const u32 sbase = smem_u32(gsm);

    const int tid = threadIdx.x;
    const int w = tid >> 5, lane = tid & 31;
    const int bm = blockIdx.x;
    const int rg = w >> 2, cg = w & 3;
    const int grp = lane >> 2;
    const int tig = lane & 3;
    const int r0 = rg * 16;

    const u32 x_off[2]  = { sbase + GOFF_X0,  sbase + GOFF_X1 };
    const u32 wf_off[2] = { sbase + GOFF_WF0, sbase + GOFF_WF1 };

    auto stage = [&](int s, int sel) {
#pragma unroll
        for (int q = 0; q < 2; ++q) {
            int v = (q << 9) + tid;
            int row = v >> 3, c4 = (v & 7) << 2;
            cpasync16(x_off[sel] + (u32)(row * XROW + c4) * 4u,
                      A + (size_t)(bm * 128 + row) * Dd + (s << 5) + c4);
        }
#pragma unroll
        for (int q = 0; q < 2; ++q) {
            int v = (q << 9) + tid;       // 0..1023
            int bn = v >> 8;
            int rest = v & 255;
            const uint4* src = (const uint4*)(g_wf16 + (size_t)((bn * 16 + (s << 1)) * 8) * 32) + rest;
            cpasync16(wf_off[sel] + (u32)(bn * 256 + rest) * 16u, src);
        }
    };

    float acc0[8][4], acc1[8][4];
#pragma unroll
    for (int n = 0; n < 8; ++n)
#pragma unroll
        for (int k = 0; k < 4; ++k) { acc0[n][k] = 0.f; acc1[n][k] = 0.f; }

    stage(0, 0); CP_COMMIT();

    for (int s = 0; s < 8; ++s) {
        const int sel = s & 1;
        if (s < 7) { stage(s + 1, sel ^ 1); CP_COMMIT(); }
        if (s < 7) CP_WAIT1(); else CP_WAIT0();
        __syncthreads();

        const float* xs = (const float*)(gsm + (sel ? GOFF_X1 : GOFF_X0));
        const uint2* wfs = (const uint2*)(gsm + (sel ? GOFF_WF1 : GOFF_WF0));

#pragma unroll
        for (int kb = 0; kb < 2; ++kb) {
            const int kc = (kb << 4) + (tig << 1);
            float2 v0a = *(const float2*)&xs[(r0 + grp) * XROW + kc];
            float2 v0b = *(const float2*)&xs[(r0 + grp) * XROW + kc + 8];
            float2 v1a = *(const float2*)&xs[(r0 + 8 + grp) * XROW + kc];
            float2 v1b = *(const float2*)&xs[(r0 + 8 + grp) * XROW + kc + 8];
            float2 v2a = *(const float2*)&xs[(64 + r0 + grp) * XROW + kc];
            float2 v2b = *(const float2*)&xs[(64 + r0 + grp) * XROW + kc + 8];
            float2 v3a = *(const float2*)&xs[(64 + r0 + 8 + grp) * XROW + kc];
            float2 v3b = *(const float2*)&xs[(64 + r0 + 8 + grp) * XROW + kc + 8];
            u32 a0 = packhf(v0a.x, v0a.y);
            u32 a1 = packhf(v1a.x, v1a.y);
            u32 a2 = packhf(v0b.x, v0b.y);
            u32 a3 = packhf(v1b.x, v1b.y);
            u32 a4 = packhf(v2a.x, v2a.y);
            u32 a5 = packhf(v3a.x, v3a.y);
            u32 a6 = packhf(v2b.x, v2b.y);
            u32 a7 = packhf(v3b.x, v3b.y);
            const uint2* wr = wfs + (((cg << 1) + kb) << 8) + lane;
#pragma unroll
            for (int n = 0; n < 8; ++n) {
                uint2 bf = wr[n << 5];
                mma16n8k16hf(acc0[n], a0, a1, a2, a3, bf.x, bf.y);
                mma16n8k16hf(acc1[n], a4, a5, a6, a7, bf.x, bf.y);
            }
        }
        __syncthreads();
    }

    // ---- e_src/e_dst: warp-local ----
    {
        float ps0 = 0.f, ps1 = 0.f, pd0 = 0.f, pd1 = 0.f;
        float qs0 = 0.f, qs1 = 0.f, qd0 = 0.f, qd1 = 0.f;
#pragma unroll
        for (int n = 0; n < 8; ++n) {
            float2 asv = *(const float2*)&a_src[cg * 64 + (n << 3) + (tig << 1)];
            float2 adv = *(const float2*)&a_dst[cg * 64 + (n << 3) + (tig << 1)];
            ps0 = fmaf(acc0[n][0], asv.x, fmaf(acc0[n][1], asv.y, ps0));
            ps1 = fmaf(acc0[n][2], asv.x, fmaf(acc0[n][3], asv.y, ps1));
            pd0 = fmaf(acc0[n][0], adv.x, fmaf(acc0[n][1], adv.y, pd0));
            pd1 = fmaf(acc0[n][2], adv.x, fmaf(acc0[n][3], adv.y, pd1));
            qs0 = fmaf(acc1[n][0], asv.x, fmaf(acc1[n][1], asv.y, qs0));
            qs1 = fmaf(acc1[n][2], asv.x, fmaf(acc1[n][3], asv.y, qs1));
            qd0 = fmaf(acc1[n][0], adv.x, fmaf(acc1[n][1], adv.y, qd0));
            qd1 = fmaf(acc1[n][2], adv.x, fmaf(acc1[n][3], adv.y, qd1));
        }
#pragma unroll
        for (int o = 1; o < 4; o <<= 1) {
            ps0 += __shfl_xor_sync(0xffffffffu, ps0, o);
            ps1 += __shfl_xor_sync(0xffffffffu, ps1, o);
            pd0 += __shfl_xor_sync(0xffffffffu, pd0, o);
            pd1 += __shfl_xor_sync(0xffffffffu, pd1, o);
            qs0 += __shfl_xor_sync(0xffffffffu, qs0, o);
            qs1 += __shfl_xor_sync(0xffffffffu, qs1, o);
            qd0 += __shfl_xor_sync(0xffffffffu, qd0, o);
            qd1 += __shfl_xor_sync(0xffffffffu, qd1, o);
        }
        if (tig == 0) {
            const int base = cg * Mrows + bm * 128;
            g_es[base + r0 + grp]           = ps0 * LOG2E;
            g_es[base + r0 + 8 + grp]       = ps1 * LOG2E;
            g_ed[base + r0 + grp]           = pd0 * LOG2E;
            g_ed[base + r0 + 8 + grp]       = pd1 * LOG2E;
            g_es[base + 64 + r0 + grp]      = qs0 * LOG2E;
            g_es[base + 64 + r0 + 8 + grp]  = qs1 * LOG2E;
            g_ed[base + 64 + r0 + grp]      = qd0 * LOG2E;
            g_ed[base + 64 + r0 + 8 + grp]  = qd1 * LOG2E;
        }
    }

    // ---- per-head hs bounce + fp16 fragment emission ----
    float (*hs)[68] = (float(*)[68])gsm;
    const int b_ = bm >> 3;

    for (int hh = 0; hh < 4; ++hh) {
        __syncthreads();
        if (cg == hh) {
#pragma unroll
            for (int n = 0; n < 8; ++n) {
                const int col = (n << 3) + (tig << 1);
                hs[r0 + grp][col]          = acc0[n][0];
                hs[r0 + grp][col + 1]      = acc0[n][1];
                hs[r0 + 8 + grp][col]      = acc0[n][2];
                hs[r0 + 8 + grp][col + 1]  = acc0[n][3];
                hs[64 + r0 + grp][col]         = acc1[n][0];
                hs[64 + r0 + grp][col + 1]     = acc1[n][1];
                hs[64 + r0 + 8 + grp][col]     = acc1[n][2];
                hs[64 + r0 + 8 + grp][col + 1] = acc1[n][3];
            }
        }
        __syncthreads();

        const int bh = b_ * 4 + hh;
#pragma unroll
        for (int q2 = 0; q2 < 4; ++q2) {
            int v = (q2 << 9) + tid;       // 0..2047
            int jbl = v >> 8;
            int nf = (v >> 5) & 7;
            int ln = v & 31;
            int jl = (jbl << 4) + ((ln & 3) << 1);
            int f = (nf << 3) + (ln >> 2);
            uint2 o;
            o.x = packhf(hs[jl][f],     hs[jl + 1][f]);
            o.y = packhf(hs[jl + 8][f], hs[jl + 9][f]);
            g_hBf[(size_t)(((bh * 64 + (bm & 7) * 8 + jbl) * 8 + nf)) * 32 + ln] = o;
        }
    }
}

// ---------------------------------------------------------------------------
// Kernel 2: flash-GAT attention, fp16 m16n8k16; denominator via ones-column
// MMA (constant fp16 1.0 operand) -- no scalar den accumulation/reduction.
// ---------------------------------------------------------------------------
constexpr int ADJ_ST = 68;
constexpr int OFF_ADJ0 = 0;                    // 34816
constexpr int OFF_ADJ1 = 34816;
constexpr int OFF_HF0  = 69632;                // 8192
constexpr int OFF_HF1  = 77824;
constexpr int OFF_ES0  = 86016;                // 256
constexpr int OFF_ES1  = 86272;
constexpr int OFF_ED   = 86528;                // 512
constexpr int SMEM_ATTN = 87040;

__global__ __launch_bounds__(256, 2) void attn_kernel(const float* __restrict__ adj,
                                                      const float* __restrict__ bias,
                                                      float* __restrict__ out) {
    extern __shared__ char dsm[];
    const u32 sbase = smem_u32(dsm);
    float* ed_sm = (float*)(dsm + OFF_ED);

    const int tid = threadIdx.x;
    const int w = tid >> 5, lane = tid & 31;
    const int bh = blockIdx.y, b = bh >> 2, h = bh & 3;
    const int i0 = blockIdx.x << 7;
    const int i_w = w << 4;
    const int grp = lane >> 2;
    const int tig = lane & 3;

    const u32 adj_off[2] = { sbase + OFF_ADJ0, sbase + OFF_ADJ1 };
    const u32 hf_off[2]  = { sbase + OFF_HF0,  sbase + OFF_HF1 };
    const u32 es_off[2]  = { sbase + OFF_ES0,  sbase + OFF_ES1 };

    const float* adj_base = adj + (size_t)(b * Nn + i0) * Nn;
    const uint2* hf_base = g_hBf + (size_t)bh * 64 * 8 * 32;
    const float* es_base = g_es + h * Mrows + b * Nn;

    auto stage = [&](int jt, int sel) {
        const int j0 = jt << 6;
        const int r = tid >> 4, c4 = (tid & 15) << 2;
#pragma unroll
        for (int q = 0; q < 8; ++q)
            cpasync16(adj_off[sel] + (u32)(((q << 4) + r) * ADJ_ST + c4) * 4u,
                      adj_base + (size_t)((q << 4) + r) * Nn + j0 + c4);
        const uint4* hsrc = (const uint4*)(hf_base + (size_t)(jt * 4) * 8 * 32);
#pragma unroll
        for (int q = 0; q < 2; ++q)
            cpasync16(hf_off[sel] + (u32)((q << 8) + tid) * 16u, hsrc + (q << 8) + tid);
        if (tid < 16)
            cpasync16(es_off[sel] + (u32)tid * 16u, es_base + j0 + tid * 4);
    };

    stage(0, 0); CP_COMMIT();
    if (tid < 128) ed_sm[tid] = g_ed[h * Mrows + b * Nn + i0 + tid];

    float acc[8][4], accD[4];
#pragma unroll
    for (int n = 0; n < 8; ++n)
#pragma unroll
        for (int k = 0; k < 4; ++k) acc[n][k] = 0.f;
#pragma unroll
    for (int k = 0; k < 4; ++k) accD[k] = 0.f;

    __syncthreads();
    const float ed0 = ed_sm[i_w + grp];
    const float ed1 = ed_sm[i_w + 8 + grp];

    for (int jt = 0; jt < 16; ++jt) {
        const int sel = jt & 1;
        if (jt < 15) { stage(jt + 1, sel ^ 1); CP_COMMIT(); }
        if (jt < 15) CP_WAIT1(); else CP_WAIT0();
        __syncthreads();

        const float* adj_sm = (const float*)(dsm + (sel ? OFF_ADJ1 : OFF_ADJ0));
        const uint2* hfrag  = (const uint2*)(dsm + (sel ? OFF_HF1 : OFF_HF0));
        const float* es_sm  = (const float*)(dsm + (sel ? OFF_ES1 : OFF_ES0));

#pragma unroll
        for (int ks = 0; ks < 4; ++ks) {
            const int jj = (ks << 4) + (tig << 1);
            float2 esA = *(const float2*)&es_sm[jj];
            float2 esB = *(const float2*)&es_sm[jj + 8];
            float2 aj0 = *(const float2*)&adj_sm[(i_w + grp) * ADJ_ST + jj];
            float2 aj1 = *(const float2*)&adj_sm[(i_w + 8 + grp) * ADJ_ST + jj];
            float2 aj2 = *(const float2*)&adj_sm[(i_w + grp) * ADJ_ST + jj + 8];
            float2 aj3 = *(const float2*)&adj_sm[(i_w + 8 + grp) * ADJ_ST + jj + 8];

            float l00 = ed0 + esA.x; l00 = fmaxf(l00, 0.2f * l00);
            float l01 = ed0 + esA.y; l01 = fmaxf(l01, 0.2f * l01);
            float l02 = ed0 + esB.x; l02 = fmaxf(l02, 0.2f * l02);
            float l03 = ed0 + esB.y; l03 = fmaxf(l03, 0.2f * l03);
            float l10 = ed1 + esA.x; l10 = fmaxf(l10, 0.2f * l10);
            float l11 = ed1 + esA.y; l11 = fmaxf(l11, 0.2f * l11);
            float l12 = ed1 + esB.x; l12 = fmaxf(l12, 0.2f * l12);
            float l13 = ed1 + esB.y; l13 = fmaxf(l13, 0.2f * l13);

            float p00 = (aj0.x > 0.5f) ? ex2f(l00) : 0.f;
            float p01 = (aj0.y > 0.5f) ? ex2f(l01) : 0.f;
            float p02 = (aj2.x > 0.5f) ? ex2f(l02) : 0.f;
            float p03 = (aj2.y > 0.5f) ? ex2f(l03) : 0.f;
            float p10 = (aj1.x > 0.5f) ? ex2f(l10) : 0.f;
            float p11 = (aj1.y > 0.5f) ? ex2f(l11) : 0.f;
            float p12 = (aj3.x > 0.5f) ? ex2f(l12) : 0.f;
            float p13 = (aj3.y > 0.5f) ? ex2f(l13) : 0.f;

            const u32 a0 = packhf(p00, p01);
            const u32 a1 = packhf(p10, p11);
            const u32 a2 = packhf(p02, p03);
            const u32 a3 = packhf(p12, p13);

            const uint2* hrow = hfrag + (ks << 8) + lane;
#pragma unroll
            for (int n = 0; n < 8; ++n) {
                uint2 bf = hrow[n << 5];
                mma16n8k16hf(acc[n], a0, a1, a2, a3, bf.x, bf.y);
            }
            // denominator: B = ones  ->  accD[0]=den(grp), accD[2]=den(grp+8)
            mma16n8k16hf(accD, a0, a1, a2, a3, ONE2, ONE2);
        }
        __syncthreads();
    }

    const float inv0 = 1.0f / accD[0];
    const float inv1 = 1.0f / accD[2];

    float* o0 = out + (size_t)(b * Nn + i0 + i_w + grp) * HF + h * 64;
    float* o1 = out + (size_t)(b * Nn + i0 + i_w + 8 + grp) * HF + h * 64;
#pragma unroll
    for (int n = 0; n < 8; ++n) {
        const int col = (n << 3) + (tig << 1);
        float2 bz = *(const float2*)&bias[h * 64 + col];
        float2 r0, r1;
        r0.x = acc[n][0] * inv0 + bz.x;  r0.y = acc[n][1] * inv0 + bz.y;
        r1.x = acc[n][2] * inv1 + bz.x;  r1.y = acc[n][3] * inv1 + bz.y;
        *(float2*)&o0[col] = r0;
        *(float2*)&o1[col] = r1;
    }
}

// ---------------------------------------------------------------------------
extern "C" void kernel_launch(void* const* d_in, const int* in_sizes, int n_in,
                              void* d_out, int out_size) {
    (void)in_sizes; (void)n_in; (void)out_size;
    const float* x     = (const float*)d_in[0];
    const float* adj   = (const float*)d_in[1];
    const float* W     = (const float*)d_in[2];
    const float* a_src = (const float*)d_in[3];
    const float* a_dst = (const float*)d_in[4];
    const float* bias  = (const float*)d_in[5];
    float* out = (float*)d_out;

    cudaFuncSetAttribute(gemm_mma,
                         cudaFuncAttributeMaxDynamicSharedMemorySize, SMEM_GEMM);
    cudaFuncSetAttribute(attn_kernel,
                         cudaFuncAttributeMaxDynamicSharedMemorySize, SMEM_ATTN);

    wfrag_kernel<<<64, 256>>>(W);
    gemm_mma<<<128, 512, SMEM_GEMM>>>(x, a_src, a_dst);
    attn_kernel<<<dim3(8, 64), 256, SMEM_ATTN>>>(adj, bias, out);
}